// round 16
// baseline (speedup 1.0000x reference)
#include <cuda_runtime.h>
#include <cuda_fp16.h>
#include <cstdint>

#define N_NODES  100000
#define N_EDGES  1600000
#define N_GRAPHS 1000
#define SCAN_B   1024
#define N_SBLK   ((N_NODES + SCAN_B - 1) / SCAN_B)   // 98

// ---------------- scratch (static __device__, no allocs) ----------------
__device__ float g_dinv[N_NODES];
__device__ int   g_cnt[N_NODES];
__device__ int   g_rank[N_EDGES];
__device__ int   g_rs[N_NODES + 1];
__device__ int   g_bsum[N_SBLK];
__device__ int2  g_csr[N_EDGES];          // {src, raw w as bits}
__device__ __align__(16) __half g_m [N_NODES * 64];  // layer0 transform (scaled in degdinv_scale)
__device__ __align__(16) __half g_h [N_NODES * 64];  // layer0 output, fp16
__device__ __align__(16) __half g_m2[N_NODES * 32];  // layer1 transform (scaled in gemm1 epilogue)
__device__ float g_pool[N_GRAPHS * 32];

// ---------------- in-degree count + rank capture (4 edges/thread) ----------------
__global__ void edge_prep_kernel(const int* __restrict__ dst, int E) {
    int e0 = (blockIdx.x * blockDim.x + threadIdx.x) * 4;
    if (e0 + 3 >= E) {
        for (int e = e0; e < E; e++)
            g_rank[e] = atomicAdd(&g_cnt[dst[e]], 1);
        return;
    }
    int4 d4 = *reinterpret_cast<const int4*>(dst + e0);
    int4 r4;
    r4.x = atomicAdd(&g_cnt[d4.x], 1);
    r4.y = atomicAdd(&g_cnt[d4.y], 1);
    r4.z = atomicAdd(&g_cnt[d4.z], 1);
    r4.w = atomicAdd(&g_cnt[d4.w], 1);
    *reinterpret_cast<int4*>(g_rank + e0) = r4;
}

// ---------------- scan stage 1 ----------------
__global__ void scan1_kernel(int n) {
    __shared__ int wsum[32];
    int i = blockIdx.x * SCAN_B + threadIdx.x;
    int lane = threadIdx.x & 31, wid = threadIdx.x >> 5;
    if (i == 0) g_rs[0] = 0;

    int v = (i < n) ? g_cnt[i] : 0;
    int s = v;
#pragma unroll
    for (int o = 1; o < 32; o <<= 1) {
        int t = __shfl_up_sync(0xffffffffu, s, o);
        if (lane >= o) s += t;
    }
    if (lane == 31) wsum[wid] = s;
    __syncthreads();
    if (wid == 0) {
        int ws = wsum[lane];
#pragma unroll
        for (int o = 1; o < 32; o <<= 1) {
            int t = __shfl_up_sync(0xffffffffu, ws, o);
            if (lane >= o) ws += t;
        }
        wsum[lane] = ws;
    }
    __syncthreads();
    int off = (wid > 0) ? wsum[wid - 1] : 0;
    int incl = s + off;
    if (i < n) g_rs[i + 1] = incl;
    if (threadIdx.x == SCAN_B - 1) g_bsum[blockIdx.x] = incl;
}

// ---------------- scan stage 2+3 merged ----------------
__global__ void scan23_kernel(int n) {
    __shared__ int pref;
    if (blockIdx.x == 0) return;
    if (threadIdx.x == 0) {
        int s = 0;
        for (int j = 0; j < (int)blockIdx.x; j++) s += g_bsum[j];
        pref = s;
    }
    __syncthreads();
    int i = blockIdx.x * SCAN_B + threadIdx.x;
    if (i < n) g_rs[i + 1] += pref;
}

// ---------------- scatter: csr[pos] = {src, raw w} over [begin, end) ----------------
__global__ void scatter_kernel(const int* __restrict__ src, const int* __restrict__ dst,
                               const float* __restrict__ w, int begin, int end) {
    int e0 = begin + (blockIdx.x * blockDim.x + threadIdx.x) * 4;
    if (e0 >= end) return;
    if (e0 + 3 >= end) {
        for (int e = e0; e < end; e++) {
            int pos = g_rs[dst[e]] + g_rank[e];
            g_csr[pos] = make_int2(src[e], __float_as_int(w[e]));
        }
        return;
    }
    int4   s4 = *reinterpret_cast<const int4*>(src + e0);
    int4   d4 = *reinterpret_cast<const int4*>(dst + e0);
    int4   r4 = *reinterpret_cast<const int4*>(g_rank + e0);
    float4 w4 = *reinterpret_cast<const float4*>(w + e0);

    g_csr[g_rs[d4.x] + r4.x] = make_int2(s4.x, __float_as_int(w4.x));
    g_csr[g_rs[d4.y] + r4.y] = make_int2(s4.y, __float_as_int(w4.y));
    g_csr[g_rs[d4.z] + r4.z] = make_int2(s4.z, __float_as_int(w4.z));
    g_csr[g_rs[d4.w] + r4.w] = make_int2(s4.w, __float_as_int(w4.w));
}

// ---------------- deg + dinv from the CSR, then scale m row in place (m' = dinv*m) -----
__global__ void degdinv_scale_kernel(__half* __restrict__ m, int n) {
    int i = blockIdx.x * blockDim.x + threadIdx.x;
    if (i >= n) return;
    float s = 1.0f;                 // self loop weight
    int p1 = g_rs[i + 1];
    for (int p = g_rs[i]; p < p1; p++)
        s += __int_as_float(g_csr[p].y);
    float di = rsqrtf(fmaxf(s, 1e-12f));
    g_dinv[i] = di;

    uint4* row = reinterpret_cast<uint4*>(m + (size_t)i * 64);
#pragma unroll
    for (int j = 0; j < 8; j++) {
        uint4 raw = row[j];
        __half2* hp = reinterpret_cast<__half2*>(&raw);
#pragma unroll
        for (int q = 0; q < 4; q++) {
            float2 v = __half22float2(hp[q]);
            hp[q] = __floats2half2_rn(v.x * di, v.y * di);
        }
        row[j] = raw;
    }
}

// ---------------- fp16 tensor-core GEMM: out[N,M] = X[N,K] @ W[K,M], fp16 out ----------------
// mma.m16n8k16.f32.f16.f16.f32. 256 threads, TR=128 rows; warp w owns rows 16w..16w+15.
// Xs: [TR][KP+8] halves (row-major k), Ws: [M][KP+8] halves (transposed, n-major).
__device__ __forceinline__ void cvt8h(const float* v, __half2* o) {
#pragma unroll
    for (int j = 0; j < 4; j++) o[j] = __floats2half2_rn(v[j * 2], v[j * 2 + 1]);
}

template <typename T, int K, int M, int TR, int KP, bool SCALE>
__global__ void __launch_bounds__(256)
gemm_f16_kernel(const T* __restrict__ X, const float* __restrict__ W,
                __half* __restrict__ out, int nrows) {
    constexpr int XSH = KP + 8;
    constexpr int WSH = KP + 8;
    __shared__ __align__(16) __half Xs[TR * XSH];
    __shared__ __align__(16) __half Ws[M * WSH];

    int row0 = blockIdx.x * TR;
    int nr = nrows - row0; if (nr > TR) nr = TR;
    int tid = threadIdx.x;
    int warp = tid >> 5, lane = tid & 31;
    int lg = lane >> 2, lt = lane & 3;

    float acc[M / 8][4];
#pragma unroll
    for (int nt = 0; nt < M / 8; nt++)
#pragma unroll
        for (int j = 0; j < 4; j++) acc[nt][j] = 0.f;

    for (int ph = 0; ph < K; ph += KP) {
        // stage W transposed: read k-row chunks coalesced, write Ws[m][k]
        for (int i = tid; i < KP * (M / 8); i += 256) {
            int r = i / (M / 8), c8 = (i % (M / 8)) * 8;
            float4 a = *reinterpret_cast<const float4*>(W + (size_t)(ph + r) * M + c8);
            float4 b = *reinterpret_cast<const float4*>(W + (size_t)(ph + r) * M + c8 + 4);
            float v[8] = {a.x, a.y, a.z, a.w, b.x, b.y, b.z, b.w};
#pragma unroll
            for (int j = 0; j < 8; j++)
                Ws[(c8 + j) * WSH + r] = __float2half_rn(v[j]);
        }
        // stage X: 8 halves per iter as one 16B STS
        for (int i = tid; i < nr * (KP / 8); i += 256) {
            int r = i / (KP / 8), c8 = (i % (KP / 8)) * 8;
            const T* xp = X + (size_t)(row0 + r) * K + ph + c8;
            __align__(16) __half2 o[4];
            if (sizeof(T) == 2) {
                *reinterpret_cast<uint4*>(o) = *reinterpret_cast<const uint4*>(xp);
            } else {
                float4 a = *reinterpret_cast<const float4*>((const float*)xp);
                float4 b = *reinterpret_cast<const float4*>((const float*)xp + 4);
                float v[8] = {a.x, a.y, a.z, a.w, b.x, b.y, b.z, b.w};
                cvt8h(v, o);
            }
            *reinterpret_cast<uint4*>(&Xs[r * XSH + c8]) = *reinterpret_cast<uint4*>(o);
        }
        __syncthreads();

        int R = warp * 16;
#pragma unroll
        for (int kc = 0; kc < KP; kc += 16) {
            uint32_t a0 = *reinterpret_cast<const uint32_t*>(&Xs[(R + lg) * XSH + kc + lt * 2]);
            uint32_t a1 = *reinterpret_cast<const uint32_t*>(&Xs[(R + lg + 8) * XSH + kc + lt * 2]);
            uint32_t a2 = *reinterpret_cast<const uint32_t*>(&Xs[(R + lg) * XSH + kc + lt * 2 + 8]);
            uint32_t a3 = *reinterpret_cast<const uint32_t*>(&Xs[(R + lg + 8) * XSH + kc + lt * 2 + 8]);
#pragma unroll
            for (int nt = 0; nt < M / 8; nt++) {
                uint32_t b0 = *reinterpret_cast<const uint32_t*>(&Ws[(nt * 8 + lg) * WSH + kc + lt * 2]);
                uint32_t b1 = *reinterpret_cast<const uint32_t*>(&Ws[(nt * 8 + lg) * WSH + kc + lt * 2 + 8]);
                asm volatile(
                    "mma.sync.aligned.m16n8k16.row.col.f32.f16.f16.f32 "
                    "{%0,%1,%2,%3}, {%4,%5,%6,%7}, {%8,%9}, {%0,%1,%2,%3};"
                    : "+f"(acc[nt][0]), "+f"(acc[nt][1]), "+f"(acc[nt][2]), "+f"(acc[nt][3])
                    : "r"(a0), "r"(a1), "r"(a2), "r"(a3), "r"(b0), "r"(b1));
            }
        }
        __syncthreads();
    }

    int r_lo = row0 + warp * 16 + lg;
    int r_hi = r_lo + 8;
    float dlo = 1.f, dhi = 1.f;
    if (SCALE) {
        dlo = (r_lo < nrows) ? g_dinv[r_lo] : 0.f;
        dhi = (r_hi < nrows) ? g_dinv[r_hi] : 0.f;
    }
#pragma unroll
    for (int nt = 0; nt < M / 8; nt++) {
        if (r_lo < nrows) {
            __half2 v = __floats2half2_rn(acc[nt][0] * dlo, acc[nt][1] * dlo);
            reinterpret_cast<__half2*>(out + (size_t)r_lo * M)[nt * 4 + lt] = v;
        }
        if (r_hi < nrows) {
            __half2 v = __floats2half2_rn(acc[nt][2] * dhi, acc[nt][3] * dhi);
            reinterpret_cast<__half2*>(out + (size_t)r_hi * M)[nt * 4 + lt] = v;
        }
    }
}

// ---------------- agg layer0: h = relu(di*(m'[d] + sum w*m'[s]) + b), fp16 in/out ----------------
__global__ void node_agg0_kernel(const __half* __restrict__ m, const float* __restrict__ b,
                                 __half* __restrict__ h, int n) {
    int gid = (blockIdx.x * blockDim.x + threadIdx.x) >> 3;
    int ft = threadIdx.x & 7;
    if (gid >= n) return;
    const uint4* m4 = reinterpret_cast<const uint4*>(m);   // row stride 8 uint4

    float acc[8];
    {
        uint4 raw = m4[(size_t)gid * 8 + ft];
        const __half2* hp = reinterpret_cast<const __half2*>(&raw);
#pragma unroll
        for (int j = 0; j < 4; j++) {
            float2 v = __half22float2(hp[j]);
            acc[j * 2 + 0] = v.x;
            acc[j * 2 + 1] = v.y;
        }
    }

    int p = g_rs[gid], p1 = g_rs[gid + 1];
    for (; p + 1 < p1; p += 2) {
        int2 c0 = g_csr[p], c1 = g_csr[p + 1];
        float w0 = __int_as_float(c0.y), w1 = __int_as_float(c1.y);
        uint4 r0 = m4[(size_t)c0.x * 8 + ft];
        uint4 r1 = m4[(size_t)c1.x * 8 + ft];
        const __half2* h0 = reinterpret_cast<const __half2*>(&r0);
        const __half2* h1 = reinterpret_cast<const __half2*>(&r1);
#pragma unroll
        for (int j = 0; j < 4; j++) {
            float2 v0 = __half22float2(h0[j]);
            float2 v1 = __half22float2(h1[j]);
            acc[j * 2 + 0] += v0.x * w0 + v1.x * w1;
            acc[j * 2 + 1] += v0.y * w0 + v1.y * w1;
        }
    }
    if (p < p1) {
        int2 c0 = g_csr[p];
        float w0 = __int_as_float(c0.y);
        uint4 r0 = m4[(size_t)c0.x * 8 + ft];
        const __half2* h0 = reinterpret_cast<const __half2*>(&r0);
#pragma unroll
        for (int j = 0; j < 4; j++) {
            float2 v0 = __half22float2(h0[j]);
            acc[j * 2 + 0] += v0.x * w0;
            acc[j * 2 + 1] += v0.y * w0;
        }
    }

    float di = g_dinv[gid];
    const float* bp = b + ft * 8;
    __align__(16) __half2 o[4];
#pragma unroll
    for (int j = 0; j < 4; j++) {
        float r0 = fmaxf(acc[j * 2 + 0] * di + bp[j * 2 + 0], 0.f);
        float r1 = fmaxf(acc[j * 2 + 1] * di + bp[j * 2 + 1], 0.f);
        o[j] = __floats2half2_rn(r0, r1);
    }
    *reinterpret_cast<uint4*>(h + (size_t)gid * 64 + ft * 8) = *reinterpret_cast<uint4*>(o);
}

// ---------------- agg layer1 + fused pooling into g_pool ----------------
__global__ void node_agg1_pool_kernel(const __half* __restrict__ m, const float* __restrict__ b,
                                      const int* __restrict__ ngi, int n) {
    int gid = (blockIdx.x * blockDim.x + threadIdx.x) >> 2;
    int ft = threadIdx.x & 3;
    if (gid >= n) return;
    const uint4* m4 = reinterpret_cast<const uint4*>(m);   // row stride 4 uint4

    float acc[8];
    {
        uint4 raw = m4[(size_t)gid * 4 + ft];
        const __half2* hp = reinterpret_cast<const __half2*>(&raw);
#pragma unroll
        for (int j = 0; j < 4; j++) {
            float2 v = __half22float2(hp[j]);
            acc[j * 2 + 0] = v.x;
            acc[j * 2 + 1] = v.y;
        }
    }

    int p = g_rs[gid], p1 = g_rs[gid + 1];
    for (; p + 1 < p1; p += 2) {
        int2 c0 = g_csr[p], c1 = g_csr[p + 1];
        float w0 = __int_as_float(c0.y), w1 = __int_as_float(c1.y);
        uint4 r0 = m4[(size_t)c0.x * 4 + ft];
        uint4 r1 = m4[(size_t)c1.x * 4 + ft];
        const __half2* h0 = reinterpret_cast<const __half2*>(&r0);
        const __half2* h1 = reinterpret_cast<const __half2*>(&r1);
#pragma unroll
        for (int j = 0; j < 4; j++) {
            float2 v0 = __half22float2(h0[j]);
            float2 v1 = __half22float2(h1[j]);
            acc[j * 2 + 0] += v0.x * w0 + v1.x * w1;
            acc[j * 2 + 1] += v0.y * w0 + v1.y * w1;
        }
    }
    if (p < p1) {
        int2 c0 = g_csr[p];
        float w0 = __int_as_float(c0.y);
        uint4 r0 = m4[(size_t)c0.x * 4 + ft];
        const __half2* h0 = reinterpret_cast<const __half2*>(&r0);
#pragma unroll
        for (int j = 0; j < 4; j++) {
            float2 v0 = __half22float2(h0[j]);
            acc[j * 2 + 0] += v0.x * w0;
            acc[j * 2 + 1] += v0.y * w0;
        }
    }

    float di = g_dinv[gid];
    const float* bp = b + ft * 8;
    float v0 = fmaxf(acc[0] * di + bp[0], 0.f);
    float v1 = fmaxf(acc[1] * di + bp[1], 0.f);
    float v2 = fmaxf(acc[2] * di + bp[2], 0.f);
    float v3 = fmaxf(acc[3] * di + bp[3], 0.f);
    float v4 = fmaxf(acc[4] * di + bp[4], 0.f);
    float v5 = fmaxf(acc[5] * di + bp[5], 0.f);
    float v6 = fmaxf(acc[6] * di + bp[6], 0.f);
    float v7 = fmaxf(acc[7] * di + bp[7], 0.f);

    int graph = ngi[gid];
    float* pp = &g_pool[graph * 32 + ft * 8];
    asm volatile("red.global.add.v4.f32 [%0], {%1, %2, %3, %4};"
                 :: "l"(pp), "f"(v0), "f"(v1), "f"(v2), "f"(v3) : "memory");
    asm volatile("red.global.add.v4.f32 [%0], {%1, %2, %3, %4};"
                 :: "l"(pp + 4), "f"(v4), "f"(v5), "f"(v6), "f"(v7) : "memory");
}

// ---------------- MLP head + scratch cleanup for the next replay ----------------
__global__ void mlp_kernel(const float* __restrict__ Wm1, const float* __restrict__ bm1,
                           const float* __restrict__ Wm2, const float* __restrict__ bm2,
                           float* __restrict__ out) {
    __shared__ float gs[32];
    __shared__ float g2s[128];
    int b = blockIdx.x, t = threadIdx.x;

    int idx = b * 128 + t;
    if (idx < N_NODES) g_cnt[idx] = 0;

    if (t < 32) {
        gs[t] = g_pool[b * 32 + t];
        g_pool[b * 32 + t] = 0.f;      // same thread read-then-zero: safe
    }
    __syncthreads();
    float a1 = bm1[t];
#pragma unroll
    for (int k = 0; k < 32; k++) a1 += gs[k] * Wm1[k * 128 + t];
    g2s[t] = fmaxf(a1, 0.f);
    __syncthreads();
    if (t < 2) {
        float a = bm2[t];
#pragma unroll
        for (int k = 0; k < 128; k++) a += g2s[k] * Wm2[k * 2 + t];
        out[b * 2 + t] = a;
    }
}

// ---------------- host ----------------
extern "C" void kernel_launch(void* const* d_in, const int* in_sizes, int n_in,
                              void* d_out, int out_size) {
    const float* x   = (const float*)d_in[0];
    const int*   ei  = (const int*)d_in[1];
    const float* ew  = (const float*)d_in[2];
    const int*   ngi = (const int*)d_in[3];
    const float* W0  = (const float*)d_in[4];
    const float* b0  = (const float*)d_in[5];
    const float* W1  = (const float*)d_in[6];
    const float* b1  = (const float*)d_in[7];
    const float* Wm1 = (const float*)d_in[8];
    const float* bm1 = (const float*)d_in[9];
    const float* Wm2 = (const float*)d_in[10];
    const float* bm2 = (const float*)d_in[11];
    float* out = (float*)d_out;

    const int* srcp = ei;
    const int* dstp = ei + N_EDGES;

    static cudaStream_t s2 = nullptr;
    static cudaEvent_t  e_fork = nullptr, e_scan = nullptr, e_sc1 = nullptr, e_join = nullptr;
    if (s2 == nullptr) {
        cudaStreamCreateWithFlags(&s2, cudaStreamNonBlocking);
        cudaEventCreateWithFlags(&e_fork, cudaEventDisableTiming);
        cudaEventCreateWithFlags(&e_scan, cudaEventDisableTiming);
        cudaEventCreateWithFlags(&e_sc1,  cudaEventDisableTiming);
        cudaEventCreateWithFlags(&e_join, cudaEventDisableTiming);
    }

    void *p_m, *p_h, *p_m2;
    cudaGetSymbolAddress(&p_m,  g_m);
    cudaGetSymbolAddress(&p_h,  g_h);
    cudaGetSymbolAddress(&p_m2, g_m2);

    const int EH = N_EDGES / 2;            // 800000, divisible by 4

    // ---- fork ----
    cudaEventRecord(e_fork, 0);
    cudaStreamWaitEvent(s2, e_fork, 0);

    // s2: count/rank + scan
    edge_prep_kernel<<<(N_EDGES / 4 + 255) / 256, 256, 0, s2>>>(dstp, N_EDGES);
    scan1_kernel<<<N_SBLK, SCAN_B, 0, s2>>>(N_NODES);
    scan23_kernel<<<N_SBLK, SCAN_B, 0, s2>>>(N_NODES);
    cudaEventRecord(e_scan, s2);

    // main: layer-0 GEMM (fp16 MMA) concurrent with the scan chain, then scatter half B
    gemm_f16_kernel<float, 128, 64, 128, 64, false>
        <<<(N_NODES + 127) / 128, 256>>>(x, W0, (__half*)p_m, N_NODES);
    cudaStreamWaitEvent(0, e_scan, 0);
    scatter_kernel<<<(EH / 4 + 255) / 256, 256>>>(srcp, dstp, ew, EH, N_EDGES);
    cudaEventRecord(e_sc1, 0);

    // s2: scatter half A, then deg+dinv+scale(m) after both halves (and after gemm0)
    scatter_kernel<<<(EH / 4 + 255) / 256, 256, 0, s2>>>(srcp, dstp, ew, 0, EH);
    cudaStreamWaitEvent(s2, e_sc1, 0);
    degdinv_scale_kernel<<<(N_NODES + 255) / 256, 256, 0, s2>>>((__half*)p_m, N_NODES);
    cudaEventRecord(e_join, s2);

    // ---- join, then the serial tail on main ----
    cudaStreamWaitEvent(0, e_join, 0);

    node_agg0_kernel<<<(N_NODES * 8 + 255) / 256, 256>>>((const __half*)p_m, b0, (__half*)p_h, N_NODES);
    gemm_f16_kernel<__half, 64, 32, 128, 64, true>
        <<<(N_NODES + 127) / 128, 256>>>((const __half*)p_h, W1, (__half*)p_m2, N_NODES);
    node_agg1_pool_kernel<<<(N_NODES * 4 + 255) / 256, 256>>>((const __half*)p_m2, b1, ngi, N_NODES);

    mlp_kernel<<<N_GRAPHS, 128>>>(Wm1, bm1, Wm2, bm2, out);
}